// round 1
// baseline (speedup 1.0000x reference)
#include <cuda_runtime.h>
#include <math.h>

#define T_TOK 8192
#define D_DIM 1024
#define H_DIM 4096
#define E_NUM 8

#define OUT_ELEMS (T_TOK * D_DIM)          // 8388608
#define LOGITS_OFF OUT_ELEMS

// Scratch (no allocations allowed in kernel_launch)
__device__ float g_mid[(size_t)2 * T_TOK * H_DIM];   // 2T rows x H, 256 MiB
__device__ int   g_cnt[E_NUM];
__device__ int   g_tok[E_NUM * T_TOK];
__device__ int   g_slot[E_NUM * T_TOK];
__device__ float g_wt[E_NUM * T_TOK];

// ---------------------------------------------------------------------------
// Zero the `out` region of d_out and the per-expert counters.
// ---------------------------------------------------------------------------
__global__ void zero_kernel(float* __restrict__ out) {
    size_t i = (size_t)blockIdx.x * blockDim.x + threadIdx.x;
    float4* o4 = (float4*)out;
    if (i < OUT_ELEMS / 4) o4[i] = make_float4(0.f, 0.f, 0.f, 0.f);
    if (i < E_NUM) g_cnt[i] = 0;
}

// ---------------------------------------------------------------------------
// Router: one warp per token. logits = x @ gate_w + gate_b, softmax, top-2,
// renormalize; append token to both experts' lists.
// ---------------------------------------------------------------------------
__global__ __launch_bounds__(256) void router_kernel(
    const float* __restrict__ x, const float* __restrict__ gw,
    const float* __restrict__ gb, float* __restrict__ logits_out) {
    int warp = (blockIdx.x * blockDim.x + threadIdx.x) >> 5;
    int lane = threadIdx.x & 31;
    if (warp >= T_TOK) return;
    int t = warp;

    float acc[E_NUM];
#pragma unroll
    for (int e = 0; e < E_NUM; e++) acc[e] = 0.f;

    const float* xr = x + (size_t)t * D_DIM;
    for (int d = lane; d < D_DIM; d += 32) {
        float xv = xr[d];
        const float4* g4 = (const float4*)(gw + (size_t)d * E_NUM);
        float4 a = g4[0], b = g4[1];
        acc[0] += xv * a.x; acc[1] += xv * a.y; acc[2] += xv * a.z; acc[3] += xv * a.w;
        acc[4] += xv * b.x; acc[5] += xv * b.y; acc[6] += xv * b.z; acc[7] += xv * b.w;
    }
#pragma unroll
    for (int e = 0; e < E_NUM; e++)
#pragma unroll
        for (int off = 16; off; off >>= 1)
            acc[e] += __shfl_xor_sync(0xffffffffu, acc[e], off);

    if (lane == 0) {
        float l[E_NUM];
#pragma unroll
        for (int e = 0; e < E_NUM; e++) {
            l[e] = acc[e] + gb[e];
            logits_out[t * E_NUM + e] = l[e];
        }
        // softmax (fp32)
        float m = l[0];
#pragma unroll
        for (int e = 1; e < E_NUM; e++) m = fmaxf(m, l[e]);
        float p[E_NUM], s = 0.f;
#pragma unroll
        for (int e = 0; e < E_NUM; e++) { p[e] = expf(l[e] - m); s += p[e]; }
#pragma unroll
        for (int e = 0; e < E_NUM; e++) p[e] = p[e] / s;
        // top-2 (lowest index wins ties, matching jax top_k)
        int e0 = 0;
#pragma unroll
        for (int e = 1; e < E_NUM; e++) if (p[e] > p[e0]) e0 = e;
        int e1 = (e0 == 0) ? 1 : 0;
#pragma unroll
        for (int e = 0; e < E_NUM; e++)
            if (e != e0 && p[e] > p[e1]) e1 = e;
        float denom = p[e0] + p[e1];
        float w0 = p[e0] / denom;
        float w1 = p[e1] / denom;

        int pos0 = atomicAdd(&g_cnt[e0], 1);
        g_tok[e0 * T_TOK + pos0]  = t;
        g_slot[e0 * T_TOK + pos0] = 2 * t;
        g_wt[e0 * T_TOK + pos0]   = w0;
        int pos1 = atomicAdd(&g_cnt[e1], 1);
        g_tok[e1 * T_TOK + pos1]  = t;
        g_slot[e1 * T_TOK + pos1] = 2 * t + 1;
        g_wt[e1 * T_TOK + pos1]   = w1;
    }
}

// ---------------------------------------------------------------------------
// Grouped GEMM1: mid[slot, :] = gelu( x[tok, :] @ w1[e] + b1[e] )
// Tile 128x128, K-chunk 8, 256 threads, 8x8 per thread.
// ---------------------------------------------------------------------------
#define TM 128
#define TN 128
#define TKC 8

__global__ __launch_bounds__(256) void gemm1_kernel(
    const float* __restrict__ x, const float* __restrict__ w1,
    const float* __restrict__ b1) {
    int e = blockIdx.z;
    int cnt = g_cnt[e];
    int rowbase = blockIdx.y * TM;
    if (rowbase >= cnt) return;
    int nbase = blockIdx.x * TN;
    const float* we = w1 + (size_t)e * D_DIM * H_DIM;

    __shared__ float As[TKC][TM];
    __shared__ float Bs[TKC][TN];
    __shared__ int toks_s[TM];
    __shared__ int slots_s[TM];

    int tid = threadIdx.x;
    if (tid < TM) {
        int r = rowbase + tid;
        if (r < cnt) {
            toks_s[tid]  = g_tok[e * T_TOK + r];
            slots_s[tid] = g_slot[e * T_TOK + r];
        } else {
            toks_s[tid] = 0;          // dummy row, store masked via slot
            slots_s[tid] = -1;
        }
    }
    __syncthreads();

    int tx = tid & 15, ty = tid >> 4;
    float C[8][8];
#pragma unroll
    for (int i = 0; i < 8; i++)
#pragma unroll
        for (int j = 0; j < 8; j++) C[i][j] = 0.f;

    int lm = tid >> 1;            // 0..127
    int lk = (tid & 1) * 4;       // 0 or 4
    int bk = tid >> 5;            // 0..7
    int bn = (tid & 31) * 4;      // 0..124

    const float* arow = x + (size_t)toks_s[lm] * D_DIM;

    for (int kb = 0; kb < D_DIM; kb += TKC) {
        float4 av = *(const float4*)(arow + kb + lk);
        float4 bv = *(const float4*)(we + (size_t)(kb + bk) * H_DIM + nbase + bn);
        As[lk + 0][lm] = av.x; As[lk + 1][lm] = av.y;
        As[lk + 2][lm] = av.z; As[lk + 3][lm] = av.w;
        *(float4*)&Bs[bk][bn] = bv;
        __syncthreads();
#pragma unroll
        for (int k = 0; k < TKC; k++) {
            float a[8], b[8];
            *(float4*)(a)     = *(float4*)&As[k][ty * 8];
            *(float4*)(a + 4) = *(float4*)&As[k][ty * 8 + 4];
            *(float4*)(b)     = *(float4*)&Bs[k][tx * 8];
            *(float4*)(b + 4) = *(float4*)&Bs[k][tx * 8 + 4];
#pragma unroll
            for (int i = 0; i < 8; i++)
#pragma unroll
                for (int j = 0; j < 8; j++)
                    C[i][j] += a[i] * b[j];
        }
        __syncthreads();
    }

#pragma unroll
    for (int i = 0; i < 8; i++) {
        int m = ty * 8 + i;
        int slot = slots_s[m];
        if (slot < 0) continue;
        float* dst = g_mid + (size_t)slot * H_DIM + nbase + tx * 8;
#pragma unroll
        for (int j = 0; j < 8; j++) {
            float v = C[i][j] + b1[e * H_DIM + nbase + tx * 8 + j];
            v = 0.5f * v * (1.0f + erff(v * 0.70710678118654752f));  // exact gelu
            dst[j] = v;
        }
    }
}

// ---------------------------------------------------------------------------
// Grouped GEMM2: out[tok, :] += wt * ( mid[slot, :] @ w2[e] + b2[e] )
// Deterministic: each out element receives exactly 2 atomic adds onto 0.
// ---------------------------------------------------------------------------
__global__ __launch_bounds__(256) void gemm2_kernel(
    const float* __restrict__ w2, const float* __restrict__ b2,
    float* __restrict__ out) {
    int e = blockIdx.z;
    int cnt = g_cnt[e];
    int rowbase = blockIdx.y * TM;
    if (rowbase >= cnt) return;
    int nbase = blockIdx.x * TN;
    const float* we = w2 + (size_t)e * H_DIM * D_DIM;

    __shared__ float As[TKC][TM];
    __shared__ float Bs[TKC][TN];
    __shared__ int toks_s[TM];
    __shared__ int slots_s[TM];
    __shared__ float wt_s[TM];

    int tid = threadIdx.x;
    if (tid < TM) {
        int r = rowbase + tid;
        if (r < cnt) {
            toks_s[tid]  = g_tok[e * T_TOK + r];
            slots_s[tid] = g_slot[e * T_TOK + r];
            wt_s[tid]    = g_wt[e * T_TOK + r];
        } else {
            toks_s[tid] = -1;
            slots_s[tid] = 0;
            wt_s[tid] = 0.f;
        }
    }
    __syncthreads();

    int tx = tid & 15, ty = tid >> 4;
    float C[8][8];
#pragma unroll
    for (int i = 0; i < 8; i++)
#pragma unroll
        for (int j = 0; j < 8; j++) C[i][j] = 0.f;

    int lm = tid >> 1;
    int lk = (tid & 1) * 4;
    int bk = tid >> 5;
    int bn = (tid & 31) * 4;

    const float* arow = g_mid + (size_t)slots_s[lm] * H_DIM;

    for (int kb = 0; kb < H_DIM; kb += TKC) {
        float4 av = *(const float4*)(arow + kb + lk);
        float4 bv = *(const float4*)(we + (size_t)(kb + bk) * D_DIM + nbase + bn);
        As[lk + 0][lm] = av.x; As[lk + 1][lm] = av.y;
        As[lk + 2][lm] = av.z; As[lk + 3][lm] = av.w;
        *(float4*)&Bs[bk][bn] = bv;
        __syncthreads();
#pragma unroll
        for (int k = 0; k < TKC; k++) {
            float a[8], b[8];
            *(float4*)(a)     = *(float4*)&As[k][ty * 8];
            *(float4*)(a + 4) = *(float4*)&As[k][ty * 8 + 4];
            *(float4*)(b)     = *(float4*)&Bs[k][tx * 8];
            *(float4*)(b + 4) = *(float4*)&Bs[k][tx * 8 + 4];
#pragma unroll
            for (int i = 0; i < 8; i++)
#pragma unroll
                for (int j = 0; j < 8; j++)
                    C[i][j] += a[i] * b[j];
        }
        __syncthreads();
    }

#pragma unroll
    for (int i = 0; i < 8; i++) {
        int m = ty * 8 + i;
        int tok = toks_s[m];
        if (tok < 0) continue;
        float wt = wt_s[m];
        float* dst = out + (size_t)tok * D_DIM + nbase + tx * 8;
#pragma unroll
        for (int j = 0; j < 8; j++) {
            float v = C[i][j] + b2[e * D_DIM + nbase + tx * 8 + j];
            atomicAdd(&dst[j], wt * v);
        }
    }
}

// ---------------------------------------------------------------------------
extern "C" void kernel_launch(void* const* d_in, const int* in_sizes, int n_in,
                              void* d_out, int out_size) {
    const float* x      = (const float*)d_in[0];  // [B,S,D]
    const float* gate_w = (const float*)d_in[1];  // [D,E]
    const float* gate_b = (const float*)d_in[2];  // [E]
    const float* w1     = (const float*)d_in[3];  // [E,D,H]
    const float* b1     = (const float*)d_in[4];  // [E,H]
    const float* w2     = (const float*)d_in[5];  // [E,H,D]
    const float* b2     = (const float*)d_in[6];  // [E,D]
    float* out    = (float*)d_out;
    float* logits = (float*)d_out + LOGITS_OFF;

    (void)in_sizes; (void)n_in; (void)out_size;

    // 1) zero out-region + counters
    zero_kernel<<<(OUT_ELEMS / 4 + 255) / 256, 256>>>(out);

    // 2) router: 8192 warps
    router_kernel<<<(T_TOK * 32) / 256, 256>>>(x, gate_w, gate_b, logits);

    // 3) grouped GEMM1 + gelu
    dim3 g1(H_DIM / TN, T_TOK / TM, E_NUM);
    gemm1_kernel<<<g1, 256>>>(x, w1, b1);

    // 4) grouped GEMM2 + weighted combine
    dim3 g2(D_DIM / TN, T_TOK / TM, E_NUM);
    gemm2_kernel<<<g2, 256>>>(w2, b2, out);
}

// round 3
// speedup vs baseline: 4.1457x; 4.1457x over previous
#include <cuda_runtime.h>
#include <cuda_fp16.h>
#include <math.h>
#include <stdint.h>

#define T_TOK 8192
#define D_DIM 1024
#define H_DIM 4096
#define E_NUM 8
#define OUT_ELEMS (T_TOK * D_DIM)

// ---------------- scratch ----------------
__device__ __half g_mid[(size_t)2 * T_TOK * H_DIM];   // 128 MiB, fp16
__device__ int   g_cnt[E_NUM];
__device__ int   g_tok[E_NUM * T_TOK];
__device__ int   g_slot[E_NUM * T_TOK];
__device__ float g_wt[E_NUM * T_TOK];

__device__ __forceinline__ uint32_t smem_u32(const void* p) {
    uint32_t a;
    asm("{ .reg .u64 t; cvta.to.shared.u64 t, %1; cvt.u32.u64 %0, t; }" : "=r"(a) : "l"(p));
    return a;
}
__device__ __forceinline__ void ldsm_x4(uint32_t* r, uint32_t addr) {
    asm volatile("ldmatrix.sync.aligned.m8n8.x4.shared.b16 {%0,%1,%2,%3}, [%4];"
                 : "=r"(r[0]), "=r"(r[1]), "=r"(r[2]), "=r"(r[3]) : "r"(addr));
}
__device__ __forceinline__ void ldsm_x4_t(uint32_t* r, uint32_t addr) {
    asm volatile("ldmatrix.sync.aligned.m8n8.x4.trans.shared.b16 {%0,%1,%2,%3}, [%4];"
                 : "=r"(r[0]), "=r"(r[1]), "=r"(r[2]), "=r"(r[3]) : "r"(addr));
}
__device__ __forceinline__ void mma16816(float* c, const uint32_t* a, const uint32_t* b) {
    asm volatile(
        "mma.sync.aligned.m16n8k16.row.col.f32.f16.f16.f32 "
        "{%0,%1,%2,%3}, {%4,%5,%6,%7}, {%8,%9}, {%0,%1,%2,%3};"
        : "+f"(c[0]), "+f"(c[1]), "+f"(c[2]), "+f"(c[3])
        : "r"(a[0]), "r"(a[1]), "r"(a[2]), "r"(a[3]), "r"(b[0]), "r"(b[1]));
}

// ---------------- zero + router ----------------
__global__ void zero_kernel(float* __restrict__ out) {
    size_t i = (size_t)blockIdx.x * blockDim.x + threadIdx.x;
    float4* o4 = (float4*)out;
    if (i < OUT_ELEMS / 4) o4[i] = make_float4(0.f, 0.f, 0.f, 0.f);
    if (i < E_NUM) g_cnt[i] = 0;
}

__global__ __launch_bounds__(256) void router_kernel(
    const float* __restrict__ x, const float* __restrict__ gw,
    const float* __restrict__ gb, float* __restrict__ logits_out) {
    int warp = (blockIdx.x * blockDim.x + threadIdx.x) >> 5;
    int lane = threadIdx.x & 31;
    if (warp >= T_TOK) return;
    int t = warp;

    float acc[E_NUM];
#pragma unroll
    for (int e = 0; e < E_NUM; e++) acc[e] = 0.f;
    const float* xr = x + (size_t)t * D_DIM;
    for (int d = lane; d < D_DIM; d += 32) {
        float xv = xr[d];
        const float4* g4 = (const float4*)(gw + (size_t)d * E_NUM);
        float4 a = g4[0], b = g4[1];
        acc[0] += xv * a.x; acc[1] += xv * a.y; acc[2] += xv * a.z; acc[3] += xv * a.w;
        acc[4] += xv * b.x; acc[5] += xv * b.y; acc[6] += xv * b.z; acc[7] += xv * b.w;
    }
#pragma unroll
    for (int e = 0; e < E_NUM; e++)
#pragma unroll
        for (int off = 16; off; off >>= 1)
            acc[e] += __shfl_xor_sync(0xffffffffu, acc[e], off);

    if (lane == 0) {
        float l[E_NUM];
#pragma unroll
        for (int e = 0; e < E_NUM; e++) {
            l[e] = acc[e] + gb[e];
            logits_out[t * E_NUM + e] = l[e];
        }
        float m = l[0];
#pragma unroll
        for (int e = 1; e < E_NUM; e++) m = fmaxf(m, l[e]);
        float p[E_NUM], s = 0.f;
#pragma unroll
        for (int e = 0; e < E_NUM; e++) { p[e] = expf(l[e] - m); s += p[e]; }
#pragma unroll
        for (int e = 0; e < E_NUM; e++) p[e] = p[e] / s;
        int e0 = 0;
#pragma unroll
        for (int e = 1; e < E_NUM; e++) if (p[e] > p[e0]) e0 = e;
        int e1 = (e0 == 0) ? 1 : 0;
#pragma unroll
        for (int e = 0; e < E_NUM; e++)
            if (e != e0 && p[e] > p[e1]) e1 = e;
        float denom = p[e0] + p[e1];

        int pos0 = atomicAdd(&g_cnt[e0], 1);
        g_tok[e0 * T_TOK + pos0]  = t;
        g_slot[e0 * T_TOK + pos0] = 2 * t;
        g_wt[e0 * T_TOK + pos0]   = p[e0] / denom;
        int pos1 = atomicAdd(&g_cnt[e1], 1);
        g_tok[e1 * T_TOK + pos1]  = t;
        g_slot[e1 * T_TOK + pos1] = 2 * t + 1;
        g_wt[e1 * T_TOK + pos1]   = p[e1] / denom;
    }
}

// ---------------- grouped GEMM via mma.sync m16n8k16 (fp16 in, fp32 acc) ----
// Block: 256 threads (8 warps, 2x4), tile M=128 x N=128, K-chunk 32.
#define ASTRIDE 40     // halfs per A smem row (32 + 8 pad); 80B
#define BSTRIDE 136    // halfs per B smem row (128 + 8 pad); 272B

template<int KTOT, int NTOT, bool FFN1>
__global__ __launch_bounds__(256) void moe_gemm_kernel(
    const float* __restrict__ Xsrc, const float* __restrict__ W,
    const float* __restrict__ Bias, float* __restrict__ OutP)
{
    const int NC = KTOT / 32;
    int e = blockIdx.z;
    int cnt = g_cnt[e];
    int rowbase = blockIdx.x * 128;
    if (rowbase >= cnt) return;
    int nbase = blockIdx.y * 128;
    int tid = threadIdx.x;
    int lane = tid & 31;
    int warp = tid >> 5;
    int wm = warp >> 2, wn = warp & 3;

    __shared__ __align__(16) __half Ah[2][128 * ASTRIDE];
    __shared__ __align__(16) __half Bh[2][32 * BSTRIDE];
    __shared__ int   src_s[128];
    __shared__ int   dst_s[128];
    __shared__ float wt_s[128];
    __shared__ float bias_s[128];

    if (tid < 128) {
        int r = rowbase + tid;
        int src = 0, dst = -1; float w = 0.f;
        if (r < cnt) {
            if (FFN1) { src = g_tok[e * T_TOK + r];  dst = g_slot[e * T_TOK + r]; }
            else      { src = g_slot[e * T_TOK + r]; dst = g_tok[e * T_TOK + r];
                        w = g_wt[e * T_TOK + r]; }
        }
        src_s[tid] = src; dst_s[tid] = dst; wt_s[tid] = w;
        bias_s[tid] = Bias[(size_t)e * NTOT + nbase + tid];
    }
    __syncthreads();

    // ---- loader assignments ----
    int arow = tid >> 1;              // 0..127
    int acol = (tid & 1) * 16;        // element offset within 32
    int brow = tid >> 3;              // 0..31
    int bcol = (tid & 7) * 16;        // element offset within 128

    const float* wp0 = W + (size_t)e * KTOT * NTOT + nbase + bcol;
    float4 br_[4];
    float4 arf[4];                    // FFN1 prefetch (fp32 A)
    uint4  arh[2];                    // FFN2 prefetch (fp16 A)
    const float*  apf = nullptr;
    const __half* aph = nullptr;
    if (FFN1) apf = Xsrc + (size_t)src_s[arow] * KTOT + acol;
    else      aph = g_mid + (size_t)src_s[arow] * KTOT + acol;

    // smem byte bases
    uint32_t a_sm = smem_u32(Ah);
    uint32_t b_sm = smem_u32(Bh);
    const uint32_t ABUF = 128 * ASTRIDE * 2;
    const uint32_t BBUF = 32 * BSTRIDE * 2;

    uint32_t a_st = a_sm + (uint32_t)(arow * ASTRIDE + acol) * 2;
    uint32_t b_st = b_sm + (uint32_t)(brow * BSTRIDE + bcol) * 2;

    // ldmatrix addresses
    int lr = lane & 15, lc = lane >> 4;
    uint32_t a_ld = a_sm + (uint32_t)((wm * 64 + lr) * ASTRIDE + lc * 8) * 2;
    uint32_t b_ld = b_sm + (uint32_t)(lr * BSTRIDE + wn * 32 + lc * 8) * 2;

    float acc[4][4][4];
#pragma unroll
    for (int i = 0; i < 4; i++)
#pragma unroll
        for (int j = 0; j < 4; j++)
#pragma unroll
            for (int k = 0; k < 4; k++) acc[i][j][k] = 0.f;

    // ---- prefetch chunk 0 ----
    {
        const float* wp = wp0;
#pragma unroll
        for (int j = 0; j < 4; j++) br_[j] = ((const float4*)(wp + (size_t)brow * NTOT))[j];
        if (FFN1) {
#pragma unroll
            for (int j = 0; j < 4; j++) arf[j] = ((const float4*)apf)[j];
        } else {
            arh[0] = ((const uint4*)aph)[0];
            arh[1] = ((const uint4*)aph)[1];
        }
    }

#pragma unroll 1
    for (int c = 0; c < NC; c++) {
        int buf = c & 1;
        // STS current chunk
        {
            uint32_t ad = a_st + buf * ABUF;
            if (FFN1) {
#pragma unroll
                for (int j = 0; j < 4; j++) {
                    __half2 h0 = __floats2half2_rn(arf[j].x, arf[j].y);
                    __half2 h1 = __floats2half2_rn(arf[j].z, arf[j].w);
                    asm volatile("st.shared.v2.b32 [%0], {%1, %2};" ::
                        "r"(ad + j * 8u), "r"(*(uint32_t*)&h0), "r"(*(uint32_t*)&h1) : "memory");
                }
            } else {
                asm volatile("st.shared.v4.b32 [%0], {%1,%2,%3,%4};" ::
                    "r"(ad), "r"(arh[0].x), "r"(arh[0].y), "r"(arh[0].z), "r"(arh[0].w) : "memory");
                asm volatile("st.shared.v4.b32 [%0], {%1,%2,%3,%4};" ::
                    "r"(ad + 16u), "r"(arh[1].x), "r"(arh[1].y), "r"(arh[1].z), "r"(arh[1].w) : "memory");
            }
            uint32_t bd = b_st + buf * BBUF;
#pragma unroll
            for (int j = 0; j < 4; j++) {
                __half2 h0 = __floats2half2_rn(br_[j].x, br_[j].y);
                __half2 h1 = __floats2half2_rn(br_[j].z, br_[j].w);
                asm volatile("st.shared.v2.b32 [%0], {%1, %2};" ::
                    "r"(bd + j * 8u), "r"(*(uint32_t*)&h0), "r"(*(uint32_t*)&h1) : "memory");
            }
        }
        __syncthreads();
        // prefetch next chunk
        if (c + 1 < NC) {
            int kb = (c + 1) * 32;
            const float* wp = wp0 + (size_t)kb * NTOT;
#pragma unroll
            for (int j = 0; j < 4; j++) br_[j] = ((const float4*)(wp + (size_t)brow * NTOT))[j];
            if (FFN1) {
#pragma unroll
                for (int j = 0; j < 4; j++) arf[j] = ((const float4*)(apf + kb))[j];
            } else {
                arh[0] = ((const uint4*)(aph + kb))[0];
                arh[1] = ((const uint4*)(aph + kb))[1];
            }
        }
        // mma over chunk c
#pragma unroll
        for (int ks = 0; ks < 2; ks++) {
            uint32_t afr[4][4], bfr[2][4];
#pragma unroll
            for (int mf = 0; mf < 4; mf++)
                ldsm_x4(afr[mf], a_ld + buf * ABUF + (uint32_t)(mf * 16 * ASTRIDE + ks * 16) * 2);
#pragma unroll
            for (int np = 0; np < 2; np++)
                ldsm_x4_t(bfr[np], b_ld + buf * BBUF + (uint32_t)(ks * 16 * BSTRIDE + np * 16) * 2);
#pragma unroll
            for (int mf = 0; mf < 4; mf++)
#pragma unroll
                for (int nf = 0; nf < 4; nf++)
                    mma16816(acc[mf][nf], afr[mf], &bfr[nf >> 1][(nf & 1) * 2]);
        }
    }

    // ---- epilogue ----
    int crow = lane >> 2;
    int ccol = (lane & 3) * 2;
#pragma unroll
    for (int mf = 0; mf < 4; mf++) {
#pragma unroll
        for (int half_ = 0; half_ < 2; half_++) {
            int mloc = wm * 64 + mf * 16 + crow + half_ * 8;
            int dst = dst_s[mloc];
            if (dst < 0) continue;
            float wv = wt_s[mloc];
#pragma unroll
            for (int nf = 0; nf < 4; nf++) {
                int nloc = wn * 32 + nf * 8 + ccol;
                float v0 = acc[mf][nf][half_ * 2 + 0] + bias_s[nloc];
                float v1 = acc[mf][nf][half_ * 2 + 1] + bias_s[nloc + 1];
                if (FFN1) {
                    v0 = 0.5f * v0 * (1.0f + erff(v0 * 0.70710678118654752f));
                    v1 = 0.5f * v1 * (1.0f + erff(v1 * 0.70710678118654752f));
                    __half2 h = __floats2half2_rn(v0, v1);
                    *(__half2*)(g_mid + (size_t)dst * NTOT + nbase + nloc) = h;
                } else {
                    float* o = OutP + (size_t)dst * NTOT + nbase + nloc;
                    atomicAdd(o,     wv * v0);
                    atomicAdd(o + 1, wv * v1);
                }
            }
        }
    }
}

// ---------------------------------------------------------------------------
extern "C" void kernel_launch(void* const* d_in, const int* in_sizes, int n_in,
                              void* d_out, int out_size) {
    const float* x      = (const float*)d_in[0];
    const float* gate_w = (const float*)d_in[1];
    const float* gate_b = (const float*)d_in[2];
    const float* w1     = (const float*)d_in[3];
    const float* b1     = (const float*)d_in[4];
    const float* w2     = (const float*)d_in[5];
    const float* b2     = (const float*)d_in[6];
    float* out    = (float*)d_out;
    float* logits = (float*)d_out + OUT_ELEMS;
    (void)in_sizes; (void)n_in; (void)out_size;

    zero_kernel<<<(OUT_ELEMS / 4 + 255) / 256, 256>>>(out);
    router_kernel<<<(T_TOK * 32) / 256, 256>>>(x, gate_w, gate_b, logits);

    dim3 g1(T_TOK / 128, H_DIM / 128, E_NUM);   // (64, 32, 8)
    moe_gemm_kernel<D_DIM, H_DIM, true><<<g1, 256>>>(x, w1, b1, nullptr);

    dim3 g2(T_TOK / 128, D_DIM / 128, E_NUM);   // (64, 8, 8)
    moe_gemm_kernel<H_DIM, D_DIM, false><<<g2, 256>>>(nullptr, w2, b2, out);
}